// round 3
// baseline (speedup 1.0000x reference)
#include <cuda_runtime.h>
#include <cstdint>
#include <cfloat>

#define BB 8
#define NN 1024
#define KK 20
#define BN (BB*NN)
#define EPSV 1e-5f

// ---------------- scratch (device globals; no runtime allocation) ----------------
__device__ float g_pair[(size_t)BB*NN*NN];   // 32MB pairwise affinities
__device__ float g_xt[BB*128*NN];            // transposed features (B, C, N), C<=128
__device__ float g_sq[BN];
__device__ int   g_idx[BN*KK];
__device__ float g_a[BN*512];                // W1 * x  per point  (B*N, O)
__device__ float g_d[BN*512];                // (W2-W1) * x per point
__device__ float g_ymax[BN*512];
__device__ float g_ymin[BN*512];
__device__ float g_ps1[BN*512];              // per-(b,n) partial sum of y over k
__device__ float g_ps2[BN*512];              // per-(b,n) partial sum of y^2 over k
__device__ float g_cat[BN*512];              // concatenated block outputs (B, N, 512)
__device__ float g_wta[512*512];             // W1^T   (C x O)
__device__ float g_wtd[512*512];             // (W2-W1)^T (C x O)
__device__ float g_cs1[16*512];
__device__ float g_cs2[16*512];
__device__ float g_stats[512*3];             // mean, scale(=g*rsqrt(v+eps)), beta
__device__ float g_bmax[BB*512];
__device__ float g_bmin[BB*512];
__device__ float g_bs1[BB*512];
__device__ float g_bs2[BB*512];
__device__ float g_feat[BB*512];

__device__ __forceinline__ const float* src_ptr(const float* ext, int coff) {
    return ext ? ext : (g_cat + coff);
}

// ---------------- weight transpose: wta[c*O+o] = W1[o][c], wtd = (W2-W1)^T ----------------
__global__ void k_prep_w(const float* __restrict__ w, int C, int O, int dual) {
    int i = blockIdx.x * 256 + threadIdx.x;
    if (i >= C * O) return;
    int c = i / O, o = i % O;
    if (dual) {
        float a = w[o * 2 * C + c];
        g_wta[c * O + o] = a;
        g_wtd[c * O + o] = w[o * 2 * C + C + c] - a;
    } else {
        g_wta[c * O + o] = w[o * C + c];
    }
}

// ---------------- feature transpose: g_xt[b][c][n] = src[(b*N+n)*ld + c] ----------------
__global__ void k_xt(const float* ext, int ldx, int coff, int C) {
    int i = blockIdx.x * 256 + threadIdx.x;
    if (i >= BB * C * NN) return;
    int n = i % NN;
    int c = (i / NN) % C;
    int b = i / (NN * C);
    const float* src = src_ptr(ext, coff);
    g_xt[(b * C + c) * NN + n] = src[(size_t)(b * NN + n) * ldx + c];
}

// ---------------- squared norms ----------------
__global__ void k_sq(const float* ext, int ldx, int coff, int C) {
    int r = blockIdx.x * 256 + threadIdx.x;
    if (r >= BN) return;
    const float* src = src_ptr(ext, coff) + (size_t)r * ldx;
    float s = 0.f;
    for (int c = 0; c < C; c++) { float v = src[c]; s += v * v; }
    g_sq[r] = s;
}

// ---------------- pairwise affinity: pair[b][n][m] = 2<x_n,x_m> - |x_n|^2 - |x_m|^2 ----------------
__global__ __launch_bounds__(256) void k_pair(int C) {
    __shared__ float As[16][68];
    __shared__ float Bs[16][68];
    int b  = blockIdx.z;
    int m0 = blockIdx.x * 64;
    int n0 = blockIdx.y * 64;
    const float* xt = g_xt + (size_t)b * C * NN;
    int tid = threadIdx.x;
    int ty = tid >> 4, tx = tid & 15;

    float acc[4][4];
#pragma unroll
    for (int i = 0; i < 4; i++)
#pragma unroll
        for (int j = 0; j < 4; j++) acc[i][j] = 0.f;

    for (int c0 = 0; c0 < C; c0 += 16) {
#pragma unroll
        for (int r2 = 0; r2 < 4; r2++) {
            int li = tid + 256 * r2;
            int i = li & 63, k = li >> 6;
            float va = 0.f, vb = 0.f;
            if (c0 + k < C) {
                va = xt[(c0 + k) * NN + n0 + i];
                vb = xt[(c0 + k) * NN + m0 + i];
            }
            As[k][i] = va;
            Bs[k][i] = vb;
        }
        __syncthreads();
#pragma unroll
        for (int k = 0; k < 16; k++) {
            float4 av = *(const float4*)&As[k][ty * 4];
            float4 bv = *(const float4*)&Bs[k][tx * 4];
            float ar[4] = {av.x, av.y, av.z, av.w};
            float br[4] = {bv.x, bv.y, bv.z, bv.w};
#pragma unroll
            for (int i = 0; i < 4; i++)
#pragma unroll
                for (int j = 0; j < 4; j++) acc[i][j] += ar[i] * br[j];
        }
        __syncthreads();
    }
    float sqm[4];
#pragma unroll
    for (int j = 0; j < 4; j++) sqm[j] = g_sq[b * NN + m0 + tx * 4 + j];
#pragma unroll
    for (int i = 0; i < 4; i++) {
        int n = n0 + ty * 4 + i;
        float sqn = g_sq[b * NN + n];
        float4 v;
        v.x = 2.f * acc[i][0] - sqn - sqm[0];
        v.y = 2.f * acc[i][1] - sqn - sqm[1];
        v.z = 2.f * acc[i][2] - sqn - sqm[2];
        v.w = 2.f * acc[i][3] - sqn - sqm[3];
        *(float4*)&g_pair[(size_t)b * NN * NN + (size_t)n * NN + m0 + tx * 4] = v;
    }
}

// ---------------- top-K: warp per row; lane-local sorted top-20, then 20 warp-argmax rounds ----------------
__global__ __launch_bounds__(256) void k_topk() {
    __shared__ float sv[8][32][21];
    __shared__ int   si[8][32][21];
    int warp = threadIdx.x >> 5, lane = threadIdx.x & 31;
    int r = blockIdx.x * 8 + warp;
    int b = r >> 10, n = r & 1023;
    const float* row = g_pair + (size_t)b * NN * NN + (size_t)n * NN;

    float* v = sv[warp][lane];
    int* ii = si[warp][lane];
#pragma unroll
    for (int t = 0; t < KK; t++) { v[t] = -FLT_MAX; ii[t] = 1 << 30; }

    for (int j = lane; j < NN; j += 32) {
        float p = row[j];
        if (p > v[KK - 1]) {                       // strict: equal keeps earlier (lower) index
            int pos = KK - 1;
            while (pos > 0 && v[pos - 1] < p) {    // strict: stable among ties
                v[pos] = v[pos - 1]; ii[pos] = ii[pos - 1]; pos--;
            }
            v[pos] = p; ii[pos] = j;
        }
    }
    __syncwarp();

    int ptr = 0;
    for (int t = 0; t < KK; t++) {
        float hv = (ptr < KK) ? v[ptr] : -FLT_MAX;
        int   hi = (ptr < KK) ? ii[ptr] : (1 << 30);
        float bv = hv; int bi = hi;
#pragma unroll
        for (int off = 16; off; off >>= 1) {
            float ov = __shfl_xor_sync(0xffffffffu, bv, off);
            int   oi = __shfl_xor_sync(0xffffffffu, bi, off);
            if (ov > bv || (ov == bv && oi < bi)) { bv = ov; bi = oi; }
        }
        if (hi == bi) ptr++;                       // winner lane (indices unique) advances
        if (lane == 0) g_idx[r * KK + t] = bi;
    }
}

// ---------------- tiled SGEMM: A = X @ Wt (and D = X @ Wtd) ----------------
template <bool DUAL>
__global__ __launch_bounds__(256) void k_gemm(const float* ext, int ldx, int coff, int C, int O) {
    __shared__ float Xs[16][68];
    __shared__ float Wa[16][68];
    __shared__ float Wd[16][68];
    const float* X = src_ptr(ext, coff);
    int o0 = blockIdx.x * 64;
    int m0 = blockIdx.y * 64;
    int tid = threadIdx.x;
    int ty = tid >> 4, tx = tid & 15;

    float acc[4][4], accd[4][4];
#pragma unroll
    for (int i = 0; i < 4; i++)
#pragma unroll
        for (int j = 0; j < 4; j++) { acc[i][j] = 0.f; accd[i][j] = 0.f; }

    for (int c0 = 0; c0 < C; c0 += 16) {
#pragma unroll
        for (int r2 = 0; r2 < 4; r2++) {
            int k = tid & 15;
            int i = (tid >> 4) + 16 * r2;
            float xv = 0.f;
            if (c0 + k < C) xv = X[(size_t)(m0 + i) * ldx + c0 + k];
            Xs[k][i] = xv;
        }
#pragma unroll
        for (int r2 = 0; r2 < 4; r2++) {
            int li = tid + 256 * r2;
            int o = li & 63, k = li >> 6;
            float va = 0.f, vd = 0.f;
            if (c0 + k < C) {
                va = g_wta[(c0 + k) * O + o0 + o];
                if (DUAL) vd = g_wtd[(c0 + k) * O + o0 + o];
            }
            Wa[k][o] = va;
            if (DUAL) Wd[k][o] = vd;
        }
        __syncthreads();
#pragma unroll
        for (int k = 0; k < 16; k++) {
            float4 xv = *(const float4*)&Xs[k][ty * 4];
            float4 wv = *(const float4*)&Wa[k][tx * 4];
            float xr[4] = {xv.x, xv.y, xv.z, xv.w};
            float wr[4] = {wv.x, wv.y, wv.z, wv.w};
            float wdr[4];
            if (DUAL) {
                float4 dv = *(const float4*)&Wd[k][tx * 4];
                wdr[0] = dv.x; wdr[1] = dv.y; wdr[2] = dv.z; wdr[3] = dv.w;
            }
#pragma unroll
            for (int i = 0; i < 4; i++)
#pragma unroll
                for (int j = 0; j < 4; j++) {
                    acc[i][j] += xr[i] * wr[j];
                    if (DUAL) accd[i][j] += xr[i] * wdr[j];
                }
        }
        __syncthreads();
    }
#pragma unroll
    for (int i = 0; i < 4; i++) {
        int m = m0 + ty * 4 + i;
        float4 va = make_float4(acc[i][0], acc[i][1], acc[i][2], acc[i][3]);
        *(float4*)&g_a[(size_t)m * O + o0 + tx * 4] = va;
        if (DUAL) {
            float4 vd = make_float4(accd[i][0], accd[i][1], accd[i][2], accd[i][3]);
            *(float4*)&g_d[(size_t)m * O + o0 + tx * 4] = vd;
        }
    }
}

// ---------------- gather + per-(b,n) max/min over k + partial channel sums ----------------
__global__ void k_gather(int O) {
    int r = blockIdx.x;
    int b = r >> 10;
    __shared__ int sidx[KK];
    if (threadIdx.x < KK) sidx[threadIdx.x] = g_idx[r * KK + threadIdx.x];
    __syncthreads();
    int o = threadIdx.x;
    float dv = g_d[(size_t)r * O + o];
    float ymx = -FLT_MAX, ymn = FLT_MAX, s1 = 0.f, s2 = 0.f;
#pragma unroll
    for (int k = 0; k < KK; k++) {
        float y = g_a[(size_t)(b * NN + sidx[k]) * O + o] + dv;
        ymx = fmaxf(ymx, y);
        ymn = fminf(ymn, y);
        s1 += y;
        s2 += y * y;
    }
    g_ymax[(size_t)r * O + o] = ymx;
    g_ymin[(size_t)r * O + o] = ymn;
    g_ps1[(size_t)r * O + o] = s1;
    g_ps2[(size_t)r * O + o] = s2;
}

// ---------------- deterministic channel-stat reduction (2 levels) ----------------
__global__ void k_stat1(int O) {
    int ox = threadIdx.x & 31;
    int wy = threadIdx.x >> 5;
    int o = blockIdx.x * 32 + ox;
    int ci = blockIdx.y;
    const int CH = BN / 16;
    float s1 = 0.f, s2 = 0.f;
    int r0 = ci * CH;
    for (int r = r0 + wy; r < r0 + CH; r += 8) {
        s1 += g_ps1[(size_t)r * O + o];
        s2 += g_ps2[(size_t)r * O + o];
    }
    __shared__ float sh1[8][32], sh2[8][32];
    sh1[wy][ox] = s1; sh2[wy][ox] = s2;
    __syncthreads();
    if (wy == 0) {
        for (int w = 1; w < 8; w++) { s1 += sh1[w][ox]; s2 += sh2[w][ox]; }
        g_cs1[ci * O + o] = s1;
        g_cs2[ci * O + o] = s2;
    }
}

__global__ void k_stat2(int O, const float* __restrict__ g, const float* __restrict__ be, float invcnt) {
    int o = blockIdx.x * 256 + threadIdx.x;
    if (o >= O) return;
    float s1 = 0.f, s2 = 0.f;
    for (int ci = 0; ci < 16; ci++) { s1 += g_cs1[ci * O + o]; s2 += g_cs2[ci * O + o]; }
    float m = s1 * invcnt;
    float v = s2 * invcnt - m * m;
    float sc = g[o] * rsqrtf(v + EPSV);
    g_stats[o * 3 + 0] = m;
    g_stats[o * 3 + 1] = sc;
    g_stats[o * 3 + 2] = be[o];
}

// ---------------- finalize a block: pick max/min by sign(scale), BN affine, lrelu ----------------
__global__ void k_final(int O, int coff) {
    int r = blockIdx.x;
    int o = threadIdx.x;
    float m = g_stats[o * 3 + 0];
    float sc = g_stats[o * 3 + 1];
    float be = g_stats[o * 3 + 2];
    float y = (sc >= 0.f) ? g_ymax[(size_t)r * O + o] : g_ymin[(size_t)r * O + o];
    float t = (y - m) * sc + be;
    g_cat[(size_t)r * 512 + coff + o] = (t >= 0.f) ? t : 0.2f * t;
}

// ---------------- final stage: per-(b,o) max/min over N + channel sums ----------------
__global__ void k_fred() {
    int ox = threadIdx.x & 31;
    int wy = threadIdx.x >> 5;
    int o = blockIdx.x * 32 + ox;
    int b = blockIdx.y;
    float mx = -FLT_MAX, mn = FLT_MAX, s1 = 0.f, s2 = 0.f;
    for (int n = wy; n < NN; n += 8) {
        float v = g_a[(size_t)(b * NN + n) * 512 + o];
        mx = fmaxf(mx, v);
        mn = fminf(mn, v);
        s1 += v;
        s2 += v * v;
    }
    __shared__ float smx[8][32], smn[8][32], ss1[8][32], ss2[8][32];
    smx[wy][ox] = mx; smn[wy][ox] = mn; ss1[wy][ox] = s1; ss2[wy][ox] = s2;
    __syncthreads();
    if (wy == 0) {
        for (int w = 1; w < 8; w++) {
            mx = fmaxf(mx, smx[w][ox]);
            mn = fminf(mn, smn[w][ox]);
            s1 += ss1[w][ox];
            s2 += ss2[w][ox];
        }
        g_bmax[b * 512 + o] = mx;
        g_bmin[b * 512 + o] = mn;
        g_bs1[b * 512 + o] = s1;
        g_bs2[b * 512 + o] = s2;
    }
}

__global__ void k_feat(const float* __restrict__ g5, const float* __restrict__ b5) {
    int o = blockIdx.x * 256 + threadIdx.x;
    if (o >= 512) return;
    float s1 = 0.f, s2 = 0.f;
    for (int b = 0; b < BB; b++) { s1 += g_bs1[b * 512 + o]; s2 += g_bs2[b * 512 + o]; }
    float m = s1 / 8192.f;
    float v = s2 / 8192.f - m * m;
    float sc = g5[o] * rsqrtf(v + EPSV);
    float be = b5[o];
    for (int b = 0; b < BB; b++) {
        float y = (sc >= 0.f) ? g_bmax[b * 512 + o] : g_bmin[b * 512 + o];
        float t = (y - m) * sc + be;
        g_feat[b * 512 + o] = (t >= 0.f) ? t : 0.2f * t;
    }
}

__global__ void k_out(const float* __restrict__ wemb, float* __restrict__ out) {
    int b = blockIdx.x;
    int f = threadIdx.x;  // 256
    __shared__ float fr[512];
    for (int i = threadIdx.x; i < 512; i += 256) fr[i] = g_feat[b * 512 + i];
    __syncthreads();
    float acc = 0.f;
    for (int o = 0; o < 512; o++) acc += fr[o] * wemb[f * 512 + o];
    out[b * 256 + f] = acc;
}

// ---------------- host orchestration ----------------
static void run_stage(const float* xext, int ldx, int coff, int C, int O,
                      const float* w, const float* g, const float* bb, int outcoff) {
    k_prep_w<<<(C * O + 255) / 256, 256>>>(w, C, O, 1);
    k_xt<<<(BB * C * NN + 255) / 256, 256>>>(xext, ldx, coff, C);
    k_sq<<<BN / 256, 256>>>(xext, ldx, coff, C);
    k_pair<<<dim3(NN / 64, NN / 64, BB), 256>>>(C);
    k_topk<<<BN / 8, 256>>>();
    k_gemm<true><<<dim3(O / 64, BN / 64), 256>>>(xext, ldx, coff, C, O);
    k_gather<<<BN, O>>>(O);
    k_stat1<<<dim3(O / 32, 16), 256>>>(O);
    k_stat2<<<(O + 255) / 256, 256>>>(O, g, bb, 1.0f / (float)(BN * KK));
    k_final<<<BN, O>>>(O, outcoff);
}

extern "C" void kernel_launch(void* const* d_in, const int* in_sizes, int n_in,
                              void* d_out, int out_size) {
    const float* x    = (const float*)d_in[0];
    const float* w1   = (const float*)d_in[1];
    const float* g1   = (const float*)d_in[2];
    const float* b1   = (const float*)d_in[3];
    const float* w2   = (const float*)d_in[4];
    const float* g2   = (const float*)d_in[5];
    const float* b2   = (const float*)d_in[6];
    const float* w3   = (const float*)d_in[7];
    const float* g3   = (const float*)d_in[8];
    const float* b3   = (const float*)d_in[9];
    const float* w4   = (const float*)d_in[10];
    const float* g4   = (const float*)d_in[11];
    const float* b4   = (const float*)d_in[12];
    const float* w5   = (const float*)d_in[13];
    const float* g5   = (const float*)d_in[14];
    const float* b5   = (const float*)d_in[15];
    const float* wemb = (const float*)d_in[16];
    float* out = (float*)d_out;

    // edge blocks: input (ptr, ld, coff, C) -> output channels at outcoff in g_cat
    run_stage(x,       3,   0,   3,   64, w1, g1, b1,   0);
    run_stage(nullptr, 512, 0,   64,  64, w2, g2, b2,  64);
    run_stage(nullptr, 512, 64,  64, 128, w3, g3, b3, 128);
    run_stage(nullptr, 512, 128, 128, 256, w4, g4, b4, 256);

    // final: y5 = cat @ w5^T  (512x512), stats over (b,n), per-b max over n, lrelu, @ wemb^T
    k_prep_w<<<(512 * 512 + 255) / 256, 256>>>(w5, 512, 512, 0);
    k_gemm<false><<<dim3(512 / 64, BN / 64), 256>>>(nullptr, 512, 0, 512, 512);
    k_fred<<<dim3(512 / 32, BB), 256>>>();
    k_feat<<<2, 256>>>(g5, b5);
    k_out<<<BB, 256>>>(wemb, out);
}